// round 17
// baseline (speedup 1.0000x reference)
#include <cuda_runtime.h>
#include <cuda_bf16.h>
#include <cuda_fp16.h>
#include <cstdint>

#define INP   768
#define HID   768
#define NH    8
#define HD    96
#define UPD   1536
#define FOUT  3088
#define BATCH 8
#define SEQ   1024
#define ROWS  (BATCH*SEQ)   /* 8192 */
#define CAPV  15.0f

#define NUP   (UPD + HID)          /* 2304 merged up-proj width  */
#define NSF   (HID + FOUT)         /* 3856 merged skip+fused width */
#define OFF_O (HID + 16)           /* 784  */
#define OFF_Q (HID + 784)          /* 1552 */
#define OFF_K (HID + 1552)         /* 2320 */
#define OFF_V (HID + 2320)         /* 3088 */

typedef unsigned long long ull;

// -------------------- scratch (no allocs allowed) --------------------
__device__ __align__(256) __nv_bfloat16 g_xnP  [ (size_t)ROWS*3*INP ];   // bf16 [hi|lo|hi]
__device__ __align__(256) __half        g_xcP  [ (size_t)ROWS*2*UPD ];   // fp16 [hi|lo]
__device__ __align__(256) __half        g_hn2P [ (size_t)ROWS*2*HID ];   // fp16 [hi|lo]
__device__ __align__(256) __nv_bfloat16 g_WupP [ (size_t)NUP*3*INP ];    // bf16 [hi|hi|lo]
__device__ __align__(256) __half        g_WsfP [ (size_t)NSF*2*UPD ];    // fp16 [hi|hi]
__device__ __align__(256) __half        g_WdP  [ (size_t)INP*2*HID ];    // fp16 [hi|hi]
__device__ __align__(256) float g_upM  [ (size_t)ROWS*NUP ];   // [xt | rt]
__device__ __align__(256) float g_sfM  [ (size_t)ROWS*NSF ];   // [xskip | fused]
__device__ __align__(256) float g_htB  [ (size_t)4*ROWS*HID ]; // 4 e-split partials
__device__ __align__(256) float g_dp   [ (size_t)ROWS*HID ];
__device__ __align__(256) float g_y1   [ (size_t)ROWS*HID ];
__device__ __align__(256) float g_biasM[ NSF ];
__device__ __align__(256) float g_if   [ (size_t)ROWS*16 ];   // soft-capped i(8)|f(8) per row
__device__ __align__(256) float g_ie   [ (size_t)ROWS*NH ];
__device__ __align__(256) float g_fe   [ (size_t)ROWS*NH ];

// -------------------- packed f32x2 helpers --------------------
__device__ __forceinline__ ull ffma2(ull a, ull b, ull c) {
    ull d; asm("fma.rn.f32x2 %0, %1, %2, %3;" : "=l"(d) : "l"(a), "l"(b), "l"(c)); return d;
}
__device__ __forceinline__ ull fmul2(ull a, ull b) {
    ull d; asm("mul.rn.f32x2 %0, %1, %2;" : "=l"(d) : "l"(a), "l"(b)); return d;
}
__device__ __forceinline__ ull fadd2(ull a, ull b) {
    ull d; asm("add.rn.f32x2 %0, %1, %2;" : "=l"(d) : "l"(a), "l"(b)); return d;
}
__device__ __forceinline__ ull bcast2(float x) {
    ull d; asm("mov.b64 %0, {%1, %1};" : "=l"(d) : "f"(x)); return d;
}
__device__ __forceinline__ float2 unpack2(ull v) {
    float2 f; asm("mov.b64 {%0, %1}, %2;" : "=f"(f.x), "=f"(f.y) : "l"(v)); return f;
}

// -------------------- mma / ldmatrix / cp.async helpers --------------------
static __device__ __forceinline__ uint32_t smem_u32(const void* p) {
    uint32_t a;
    asm("{ .reg .u64 t; cvta.to.shared.u64 t, %1; cvt.u32.u64 %0, t; }" : "=r"(a) : "l"(p));
    return a;
}
#define LDSM4(r, addr) \
    asm volatile("ldmatrix.sync.aligned.m8n8.x4.shared.b16 {%0,%1,%2,%3}, [%4];" \
        : "=r"((r)[0]), "=r"((r)[1]), "=r"((r)[2]), "=r"((r)[3]) : "r"(addr))
#define MMA_BF16(c, a, b0, b1) \
    asm volatile("mma.sync.aligned.m16n8k16.row.col.f32.bf16.bf16.f32 " \
        "{%0,%1,%2,%3}, {%4,%5,%6,%7}, {%8,%9}, {%0,%1,%2,%3};" \
        : "+f"((c)[0]), "+f"((c)[1]), "+f"((c)[2]), "+f"((c)[3]) \
        : "r"((a)[0]), "r"((a)[1]), "r"((a)[2]), "r"((a)[3]), "r"(b0), "r"(b1))
#define MMA_F16(c, a, b0, b1) \
    asm volatile("mma.sync.aligned.m16n8k16.row.col.f32.f16.f16.f32 " \
        "{%0,%1,%2,%3}, {%4,%5,%6,%7}, {%8,%9}, {%0,%1,%2,%3};" \
        : "+f"((c)[0]), "+f"((c)[1]), "+f"((c)[2]), "+f"((c)[3]) \
        : "r"((a)[0]), "r"((a)[1]), "r"((a)[2]), "r"((a)[3]), "r"(b0), "r"(b1))
static __device__ __forceinline__ void cp_async16(uint32_t d, const void* g, int sz) {
    asm volatile("cp.async.cg.shared.global [%0], [%1], 16, %2;"
                 :: "r"(d), "l"(g), "r"(sz) : "memory");
}
#define CP_COMMIT() asm volatile("cp.async.commit_group;" ::: "memory")
#define CP_WAIT1()  asm volatile("cp.async.wait_group 1;" ::: "memory")
#define CP_WAIT0()  asm volatile("cp.async.wait_group 0;" ::: "memory")

// 128B rows, 8 chunks of 16B, XOR-swizzled by row&7
static __device__ __forceinline__ uint32_t sw128(uint32_t base, int row, int ch) {
    return base + ((uint32_t)row << 7) + ((uint32_t)((ch ^ (row & 7)) & 7) << 4);
}

// -------------------- reduction helper --------------------
__device__ __forceinline__ void block_reduce_sum2(float& s, float& s2,
                                                  float* sh, float* sh2) {
    int lane = threadIdx.x & 31, wid = threadIdx.x >> 5;
#pragma unroll
    for (int o = 16; o > 0; o >>= 1) {
        s  += __shfl_xor_sync(0xffffffffu, s,  o);
        s2 += __shfl_xor_sync(0xffffffffu, s2, o);
    }
    if (lane == 0) { sh[wid] = s; sh2[wid] = s2; }
    __syncthreads();
    float t = 0.f, t2 = 0.f;
#pragma unroll
    for (int i = 0; i < 8; i++) { t += sh[i]; t2 += sh2[i]; }
    s = t; s2 = t2;
}

__device__ __forceinline__ void split_bf16(float x, __nv_bfloat16& hi, __nv_bfloat16& lo) {
    hi = __float2bfloat16(x);
    lo = __float2bfloat16(x - __bfloat162float(hi));
}
__device__ __forceinline__ void split_f16(float x, __half& hi, __half& lo) {
    hi = __float2half(x);
    lo = __float2half(x - __half2float(hi));
}

// -------------------- mega pack: ln1+A-pack, all weight packs, bias — one launch ------
#define NB_LN 8192
#define NB_B  4608    /* UPD*INP/256  W_up_l  */
#define NB_C  2304    /* HID*INP/256  W_up_r  */
#define NB_D  4608    /* HID*UPD/256  W_skip  */
#define NB_E  18528   /* FOUT*UPD/256 fused_W */
#define NB_F  2304    /* INP*HID/256  W_down  */
#define NB_G  16      /* bias */
#define NB_TOTAL (NB_LN + NB_B + NB_C + NB_D + NB_E + NB_F + NB_G)

__global__ __launch_bounds__(256) void mega_pack_kernel(
    const float* __restrict__ x, const float* __restrict__ ln1_g, const float* __restrict__ ln1_b,
    const float* __restrict__ W_up_l, const float* __restrict__ W_up_r,
    const float* __restrict__ W_skip, const float* __restrict__ fused_W,
    const float* __restrict__ W_down, const float* __restrict__ fused_b,
    __nv_bfloat16* __restrict__ xnP, __nv_bfloat16* __restrict__ WupP,
    __half* __restrict__ WsfP, __half* __restrict__ WdP, float* __restrict__ biasM) {
    int bid = blockIdx.x;
    int t = threadIdx.x;
    if (bid < NB_LN) {
        // ---- ln1 + bf16 3-term A-pack ----
        __shared__ float sh[8], sh2[8];
        int row = bid;
        const float* xr = x + (size_t)row * INP;
        float v0 = xr[t], v1 = xr[t + 256], v2 = xr[t + 512];
        float s = v0 + v1 + v2;
        float s2 = v0 * v0 + v1 * v1 + v2 * v2;
        block_reduce_sum2(s, s2, sh, sh2);
        float mean = s * (1.0f / INP);
        float var  = s2 * (1.0f / INP) - mean * mean;
        float r = rsqrtf(var + 1e-6f);
        __nv_bfloat16* pr = xnP + (size_t)row * 3 * INP;
#pragma unroll
        for (int k = 0; k < 3; k++) {
            int j = t + k * 256;
            float v = (k == 0) ? v0 : (k == 1) ? v1 : v2;
            float y = (v - mean) * r * ln1_g[j] + ln1_b[j];
            __nv_bfloat16 hi, lo; split_bf16(y, hi, lo);
            pr[j] = hi; pr[INP + j] = lo; pr[2 * INP + j] = hi;
        }
        return;
    }
    bid -= NB_LN;
    if (bid < NB_B) {            // W_up_l -> WupP bf16 [hi|hi|lo], K=INP
        int i = bid * 256 + t;
        int row = i / INP, j = i % INP;
        __nv_bfloat16 hi, lo; split_bf16(W_up_l[i], hi, lo);
        __nv_bfloat16* d = WupP + (size_t)row * 3 * INP;
        d[j] = hi; d[INP + j] = hi; d[2 * INP + j] = lo;
        return;
    }
    bid -= NB_B;
    if (bid < NB_C) {            // W_up_r -> WupP offset UPD rows
        int i = bid * 256 + t;
        int row = i / INP, j = i % INP;
        __nv_bfloat16 hi, lo; split_bf16(W_up_r[i], hi, lo);
        __nv_bfloat16* d = WupP + (size_t)(UPD + row) * 3 * INP;
        d[j] = hi; d[INP + j] = hi; d[2 * INP + j] = lo;
        return;
    }
    bid -= NB_C;
    if (bid < NB_D) {            // W_skip -> WsfP fp16 [hi|hi], K=UPD
        int i = bid * 256 + t;
        int row = i / UPD, j = i % UPD;
        __half hi = __float2half(W_skip[i]);
        __half* d = WsfP + (size_t)row * 2 * UPD;
        d[j] = hi; d[UPD + j] = hi;
        return;
    }
    bid -= NB_D;
    if (bid < NB_E) {            // fused_W -> WsfP offset HID rows
        int i = bid * 256 + t;
        int row = i / UPD, j = i % UPD;
        __half hi = __float2half(fused_W[i]);
        __half* d = WsfP + (size_t)(HID + row) * 2 * UPD;
        d[j] = hi; d[UPD + j] = hi;
        return;
    }
    bid -= NB_E;
    if (bid < NB_F) {            // W_down -> WdP fp16 [hi|hi], K=HID
        int i = bid * 256 + t;
        int row = i / HID, j = i % HID;
        __half hi = __float2half(W_down[i]);
        __half* d = WdP + (size_t)row * 2 * HID;
        d[j] = hi; d[HID + j] = hi;
        return;
    }
    bid -= NB_F;
    {                             // bias build
        int i = bid * 256 + t;
        if (i < NSF) biasM[i] = (i < HID) ? 0.f : fused_b[i - HID];
    }
}

// -------------------- warp-MMA NT GEMM, K64 tiles, 3-stage cp.async ------------
// 128 thr = 4 warps (2x2); block tile 128x128; warp tile 64x64; dyn smem 96KB.
// cp.async for stage it+2 issued right after the top-of-loop barrier (safe: all
// warps finished reading that buffer in iteration it-1) so loads overlap the MMAs.
template<int FP16>
__global__ __launch_bounds__(128) void gemm_mma_kernel(
    int Nn, int Kp,
    const void* __restrict__ Av, const void* __restrict__ Bv,
    const float* __restrict__ bias, float* __restrict__ Cout) {
    const __half* A = (const __half*)Av;      // 16-bit payload; dtype via FP16 flag
    const __half* B = (const __half*)Bv;
    extern __shared__ __align__(1024) char sm[];
    uint32_t sA = smem_u32(sm);            // 3 x 16KB
    uint32_t sB = sA + 49152u;             // 3 x 16KB
    int tid = threadIdx.x;
    int bm = blockIdx.y * 128, bn = blockIdx.x * 128;
    int wid = tid >> 5, lane = tid & 31;
    int wm = wid >> 1, wn = wid & 1;
    int lr = lane & 7, grp = lane >> 3;
    int niter = Kp >> 6;

    float acc[4][8][4];
#pragma unroll
    for (int i = 0; i < 4; i++)
#pragma unroll
        for (int j = 0; j < 8; j++)
#pragma unroll
            for (int q = 0; q < 4; q++) acc[i][j][q] = 0.f;

    auto issue_stage = [&](int it, int s) {
        int kt = it << 6;
#pragma unroll
        for (int q = 0; q < 8; q++) {
            int idx = tid + q * 128;
            int r = idx >> 3, ch = idx & 7;
            cp_async16(sw128(sA + (uint32_t)s * 16384u, r, ch),
                       A + (size_t)(bm + r) * Kp + kt + ch * 8, 16);
        }
#pragma unroll
        for (int q = 0; q < 8; q++) {
            int idx = tid + q * 128;
            int r = idx >> 3, ch = idx & 7;
            int br = bn + r;
            cp_async16(sw128(sB + (uint32_t)s * 16384u, r, ch),
                       B + (size_t)(br < Nn ? br : 0) * Kp + kt + ch * 8,
                       br < Nn ? 16 : 0);
        }
        CP_COMMIT();
    };

    issue_stage(0, 0);
    if (niter > 1) issue_stage(1, 1);

    for (int it = 0; it < niter; it++) {
        int s = it % 3;
        if (it + 1 < niter) CP_WAIT1(); else CP_WAIT0();
        __syncthreads();
        if (it + 2 < niter) issue_stage(it + 2, (it + 2) % 3);   // overlap with MMAs below

        uint32_t Ab = sA + (uint32_t)s * 16384u;
        uint32_t Bb = sB + (uint32_t)s * 16384u;
#pragma unroll
        for (int ks = 0; ks < 4; ks++) {
            uint32_t a[4][4];
#pragma unroll
            for (int fm = 0; fm < 4; fm++) {
                int row = wm * 64 + fm * 16 + lr + ((grp & 1) << 3);
                int ch = ks * 2 + (grp >> 1);
                LDSM4(a[fm], sw128(Ab, row, ch));
            }
            uint32_t b[4][4];
#pragma unroll
            for (int np = 0; np < 4; np++) {
                int row = wn * 64 + np * 16 + lr + ((grp >> 1) << 3);
                int ch = ks * 2 + (grp & 1);
                LDSM4(b[np], sw128(Bb, row, ch));
            }
#pragma unroll
            for (int fm = 0; fm < 4; fm++)
#pragma unroll
                for (int np = 0; np < 4; np++) {
#pragma unroll
                    for (int fl = 0; fl < 2; fl++) {
                        if (FP16) { MMA_F16(acc[fm][np * 2 + fl], a[fm], b[np][fl * 2], b[np][fl * 2 + 1]); }
                        else      { MMA_BF16(acc[fm][np * 2 + fl], a[fm], b[np][fl * 2], b[np][fl * 2 + 1]); }
                    }
                }
        }
    }

    int qr = lane >> 2, qc = lane & 3;
#pragma unroll
    for (int fn = 0; fn < 8; fn++) {
        int np = fn >> 1, fl = fn & 1;
        int col = bn + wn * 64 + np * 16 + fl * 8 + qc * 2;
        if (col < Nn) {
            float bx = bias ? bias[col] : 0.f;
            float by = bias ? bias[col + 1] : 0.f;
#pragma unroll
            for (int fm = 0; fm < 4; fm++) {
                int row0 = bm + wm * 64 + fm * 16 + qr;
                float2 v0 = make_float2(acc[fm][fn][0] + bx, acc[fm][fn][1] + by);
                float2 v1 = make_float2(acc[fm][fn][2] + bx, acc[fm][fn][3] + by);
                *(float2*)(Cout + (size_t)row0 * Nn + col) = v0;
                *(float2*)(Cout + (size_t)(row0 + 8) * Nn + col) = v1;
            }
        }
    }
}

// -------------------- causal conv + silu + fp16 2-term A-pack, float4/thread ---------
__global__ __launch_bounds__(128) void conv_silu_pack_kernel(const float* __restrict__ up,
                                                             const float* __restrict__ w,
                                                             __half* __restrict__ p) {
    int row = blockIdx.y;
    int j = (blockIdx.x * 128 + threadIdx.x) * 4;
    const float* xr = up + (size_t)row * NUP;
    float4 v = *(const float4*)(xr + j);
    float p0 = 0.f, p1 = 0.f, p2 = 0.f;
    if (j >= 4) {
        float4 pv = *(const float4*)(xr + j - 4);
        p0 = pv.w; p1 = pv.z; p2 = pv.y;
    }
    float w0 = w[0], w1 = w[1], w2 = w[2], w3 = w[3];
    float o0 = w3 * v.x + w2 * p0 + w1 * p1 + w0 * p2;
    float o1 = w3 * v.y + w2 * v.x + w1 * p0 + w0 * p1;
    float o2 = w3 * v.z + w2 * v.y + w1 * v.x + w0 * p0;
    float o3 = w3 * v.w + w2 * v.z + w1 * v.y + w0 * v.x;
    o0 = o0 / (1.0f + expf(-o0));
    o1 = o1 / (1.0f + expf(-o1));
    o2 = o2 / (1.0f + expf(-o2));
    o3 = o3 / (1.0f + expf(-o3));
    __half h0, l0, h1, l1, h2, l2, h3, l3;
    split_f16(o0, h0, l0); split_f16(o1, h1, l1);
    split_f16(o2, h2, l2); split_f16(o3, h3, l3);
    __half* pr = p + (size_t)row * 2 * UPD;
    __half2 hv0 = __halves2half2(h0, h1), hv1 = __halves2half2(h2, h3);
    __half2 lv0 = __halves2half2(l0, l1), lv1 = __halves2half2(l2, l3);
    *(uint2*)(pr + j)       = make_uint2(*(uint32_t*)&hv0, *(uint32_t*)&hv1);
    *(uint2*)(pr + UPD + j) = make_uint2(*(uint32_t*)&lv0, *(uint32_t*)&lv1);
}

// -------------------- exact gate GEMM: i/f (16 cols) from xc hi+lo, fp32 -----------
#define GW_STRIDE 1538
#define GW_SMEM (16 * GW_STRIDE * 4)
__global__ __launch_bounds__(256) void gate_kernel(const __half* __restrict__ xcP,
                                                   const float* __restrict__ fW,
                                                   const float* __restrict__ fb,
                                                   float* __restrict__ gif) {
    extern __shared__ float ws[];   // [g][k], stride 1538
    for (int idx = threadIdx.x; idx < 16 * UPD; idx += 256) {
        int g = idx / UPD, k = idx % UPD;
        ws[g * GW_STRIDE + k] = fW[idx];
    }
    __syncthreads();
    int rowl = threadIdx.x >> 4, g = threadIdx.x & 15;
    int row = blockIdx.x * 16 + rowl;
    const __half* pr = xcP + (size_t)row * 2 * UPD;
    const float* wg = ws + g * GW_STRIDE;
    float acc = 0.f;
#pragma unroll 4
    for (int k = 0; k < UPD; k += 2) {
        __half2 h2 = *(const __half2*)(pr + k);
        __half2 l2 = *(const __half2*)(pr + UPD + k);
        float2 hf = __half22float2(h2), lf = __half22float2(l2);
        float2 w2 = *(const float2*)(wg + k);
        acc = fmaf(hf.x + lf.x, w2.x, acc);
        acc = fmaf(hf.y + lf.y, w2.y, acc);
    }
    acc += fb[g];
    gif[(size_t)row * 16 + g] = CAPV * tanhf(acc * (1.0f / CAPV));
}

// -------------------- parallel max-plus scan: ie/fe per (b,h,s) --------------------
// m_t = max(f_t + m_{t-1}, i_t); segment composition (F1,I1)∘(F2,I2) = (F1+F2, max(I1+F2, I2)).
__global__ __launch_bounds__(SEQ) void mscan_kernel(const float* __restrict__ gif,
                                                    float* __restrict__ gie,
                                                    float* __restrict__ gfe,
                                                    float* __restrict__ outM) {
    __shared__ double Fs[SEQ];
    __shared__ double Is[SEQ];
    int bh = blockIdx.x;
    int b = bh >> 3, h = bh & 7;
    int s = threadIdx.x;
    const float* base = gif + (size_t)b * SEQ * 16;
    float fi = base[s * 16 + h];        // i_t
    float ff = base[s * 16 + 8 + h];    // f_t
    double F = (double)ff, I = (double)fi;
    Fs[s] = F; Is[s] = I;
    __syncthreads();
#pragma unroll
    for (int off = 1; off < SEQ; off <<= 1) {
        double Fn = F, In = I;
        if (s >= off) {
            double F1 = Fs[s - off], I1 = Is[s - off];
            Fn = F1 + F;
            In = fmax(I1 + F, I);
        }
        __syncthreads();
        Fs[s] = Fn; Is[s] = In; F = Fn; I = In;
        __syncthreads();
    }
    double M = fmax(F, I);                       // m_s (m_0 = 0)
    double Mprev = (s > 0) ? fmax(Fs[s - 1], Is[s - 1]) : 0.0;
    size_t o = ((size_t)b * SEQ + s) * NH + h;
    gie[o] = expf((float)((double)fi - M));
    gfe[o] = expf((float)((double)ff - M + Mprev));
    if (s == SEQ - 1) outM[bh] = (float)M;
}

// -------------------- sequential mLSTM scan: 4 blocks per (b,h), e-split x4 ---------
__global__ __launch_bounds__(96) void scan_kernel(const float* __restrict__ sf,
                                                  const float* __restrict__ gie,
                                                  const float* __restrict__ gfe,
                                                  float* __restrict__ htB,
                                                  float* __restrict__ dpo,
                                                  float* __restrict__ outC,
                                                  float* __restrict__ outN) {
    int bx = blockIdx.x;
    int bh = bx >> 2, sp = bx & 3;
    int b = bh >> 3, h = bh & 7;
    int e0 = sp * 24;
    int t = threadIdx.x;
    const float inv = rsqrtf((float)HD);

    ull C[12];
#pragma unroll
    for (int e = 0; e < 12; e++) C[e] = 0ull;
    float nd = 1.0f;

    __shared__ __align__(16) float qs[2][24];
    __shared__ __align__(16) float ks[2][24];

    const float* base = sf + (size_t)b * SEQ * NSF;
    const float* geb = gie + (size_t)b * SEQ * NH + h;
    const float* gfb = gfe + (size_t)b * SEQ * NH + h;
    float* htp = htB + (size_t)sp * ROWS * HID;

    float qv = 0.f, kv = 0.f;
    if (t < 24) {
        qv = base[OFF_Q + h * HD + e0 + t];
        kv = base[OFF_K + h * HD + e0 + t];
    }
    float vv = base[OFF_V + h * HD + t];
    float ie = geb[0], fe = gfb[0];

    for (int s = 0; s < SEQ; s++) {
        int p = s & 1;
        float qd = qv, kd = kv * inv, vd = vv;
        float iec = ie, fec = fe;
        if (t < 24) { qs[p][t] = qd; ks[p][t] = kd; }
        __syncthreads();

        if (s + 1 < SEQ) {
            const float* b2 = base + (size_t)(s + 1) * NSF;
            if (t < 24) {
                qv = b2[OFF_Q + h * HD + e0 + t];
                kv = b2[OFF_K + h * HD + e0 + t];
            }
            vv = b2[OFF_V + h * HD + t];
            ie = geb[(size_t)(s + 1) * NH];
            fe = gfb[(size_t)(s + 1) * NH];
        }

        ull pa  = bcast2(iec * vd);
        ull pfe = bcast2(fec);
        const ulonglong2* kp2 = (const ulonglong2*)ks[p];
        const ulonglong2* qp2 = (const ulonglong2*)qs[p];
        ull hn0 = 0ull, hn1 = 0ull, hn2a = 0ull, hn3 = 0ull;
#pragma unroll
        for (int e2 = 0; e2 < 6; e2 += 2) {
            ulonglong2 kk0 = kp2[e2],     qq0 = qp2[e2];
            ulonglong2 kk1 = kp2[e2 + 1], qq1 = qp2[e2 + 1];
            ull c;
            c = ffma2(pa, kk0.x, fmul2(pfe, C[2 * e2 + 0])); C[2 * e2 + 0] = c; hn0  = ffma2(c, qq0.x, hn0);
            c = ffma2(pa, kk0.y, fmul2(pfe, C[2 * e2 + 1])); C[2 * e2 + 1] = c; hn1  = ffma2(c, qq0.y, hn1);
            c = ffma2(pa, kk1.x, fmul2(pfe, C[2 * e2 + 2])); C[2 * e2 + 2] = c; hn2a = ffma2(c, qq1.x, hn2a);
            c = ffma2(pa, kk1.y, fmul2(pfe, C[2 * e2 + 3])); C[2 * e2 + 3] = c; hn3  = ffma2(c, qq1.y, hn3);
        }
        float2 hf = unpack2(fadd2(fadd2(hn0, hn1), fadd2(hn2a, hn3)));
        float hnv = hf.x + hf.y;

        size_t o = ((size_t)b * SEQ + s) * HID + h * HD;
        htp[o + t] = hnv;
        if (t < 24) {
            nd = fmaf(iec, kd, fec * nd);
            dpo[o + e0 + t] = nd * qd;
        }
    }

    float* Cr = outC + ((size_t)bh * HD + t) * HD + e0;
#pragma unroll
    for (int e = 0; e < 12; e++) {
        float2 f = unpack2(C[e]);
        *(float2*)(Cr + 2 * e) = f;
    }
    if (t < 24) outN[bh * HD + e0 + t] = nd;
}

// -------------------- denom reduce + o-gate, LN2, fp16 2-term A-pack ----------------
__global__ __launch_bounds__(256) void post_pack_kernel(const float* __restrict__ sf,
                                                        const float* __restrict__ htB,
                                                        const float* __restrict__ dp,
                                                        const float* __restrict__ g,
                                                        const float* __restrict__ b,
                                                        __half* __restrict__ p) {
    __shared__ float sh[8], sh2[8], sden[8];
    int row = blockIdx.x, t = threadIdx.x;
    int w = t >> 5, lane = t & 31;

    const float* dpr = dp + (size_t)row * HID;
    float sdp = dpr[w * 96 + lane] + dpr[w * 96 + 32 + lane] + dpr[w * 96 + 64 + lane];
#pragma unroll
    for (int o = 16; o > 0; o >>= 1) sdp += __shfl_xor_sync(0xffffffffu, sdp, o);
    if (lane == 0) sden[w] = fmaxf(sdp, 1.0f);
    __syncthreads();

    const float* fr = sf + (size_t)row * NSF + OFF_O;
    const float* h0 = htB + (size_t)row * HID;
    const float* h1 = h0 + (size_t)ROWS * HID;
    const float* h2 = h1 + (size_t)ROWS * HID;
    const float* h3 = h2 + (size_t)ROWS * HID;
    float hv[3]; float s = 0.f, s2 = 0.f;
#pragma unroll
    for (int k = 0; k < 3; k++) {
        int j = t + k * 256;
        float oraw = fr[j];
        float og = 1.0f / (1.0f + expf(-CAPV * tanhf(oraw * (1.0f / CAPV))));
        float h = og * (((h0[j] + h1[j]) + (h2[j] + h3[j])) / sden[j / 96]);
        hv[k] = h; s += h; s2 += h * h;
    }
    block_reduce_sum2(s, s2, sh, sh2);
    float mean = s * (1.0f / HID);
    float var  = s2 * (1.0f / HID) - mean * mean;
    float r = rsqrtf(var + 1e-6f);
    __half* pr = p + (size_t)row * 2 * HID;
#pragma unroll
    for (int k = 0; k < 3; k++) {
        int j = t + k * 256;
        float y = (hv[k] - mean) * r * g[j] + b[j];
        __half hi, lo; split_f16(y, hi, lo);
        pr[j] = hi; pr[HID + j] = lo;
    }
}

// -------------------- final fuse: (y1 + xskip)*silu(rt) + x, float4 --------------------
__global__ __launch_bounds__(192) void final_kernel(const float* __restrict__ y1,
                                                    const float* __restrict__ sf,
                                                    const float* __restrict__ up,
                                                    const float* __restrict__ x,
                                                    float* __restrict__ out) {
    int row = blockIdx.x;
    int j = threadIdx.x * 4;
    float4 yv = *(const float4*)(y1 + (size_t)row * HID + j);
    float4 sk = *(const float4*)(sf + (size_t)row * NSF + j);
    float4 rv = *(const float4*)(up + (size_t)row * NUP + UPD + j);
    float4 xv = *(const float4*)(x + (size_t)row * HID + j);
    float4 o;
    o.x = (yv.x + sk.x) * (rv.x / (1.0f + expf(-rv.x))) + xv.x;
    o.y = (yv.y + sk.y) * (rv.y / (1.0f + expf(-rv.y))) + xv.y;
    o.z = (yv.z + sk.z) * (rv.z / (1.0f + expf(-rv.z))) + xv.z;
    o.w = (yv.w + sk.w) * (rv.w / (1.0f + expf(-rv.w))) + xv.w;
    *(float4*)(out + (size_t)row * HID + j) = o;
}

// -------------------- launch --------------------
#define GEMM_SMEM (3 * 32768)

extern "C" void kernel_launch(void* const* d_in, const int* in_sizes, int n_in,
                              void* d_out, int out_size) {
    (void)in_sizes; (void)n_in; (void)out_size;
    const float* x       = (const float*)d_in[0];
    const float* ln1_g   = (const float*)d_in[1];
    const float* ln1_b   = (const float*)d_in[2];
    const float* W_up_l  = (const float*)d_in[3];
    const float* W_up_r  = (const float*)d_in[4];
    const float* conv_w  = (const float*)d_in[5];
    const float* W_skip  = (const float*)d_in[6];
    const float* fused_W = (const float*)d_in[7];
    const float* fused_b = (const float*)d_in[8];
    const float* ln2_g   = (const float*)d_in[9];
    const float* ln2_b   = (const float*)d_in[10];
    const float* W_down  = (const float*)d_in[11];
    float* out = (float*)d_out;

    __nv_bfloat16 *xnP, *WupP;
    __half *xcP, *hn2P, *WsfP, *WdP;
    float *upM, *sfM, *htB, *dp, *y1, *biasM, *gif, *gie, *gfe;
    cudaGetSymbolAddress((void**)&xnP,   g_xnP);
    cudaGetSymbolAddress((void**)&xcP,   g_xcP);
    cudaGetSymbolAddress((void**)&hn2P,  g_hn2P);
    cudaGetSymbolAddress((void**)&WupP,  g_WupP);
    cudaGetSymbolAddress((void**)&WsfP,  g_WsfP);
    cudaGetSymbolAddress((void**)&WdP,   g_WdP);
    cudaGetSymbolAddress((void**)&upM,   g_upM);
    cudaGetSymbolAddress((void**)&sfM,   g_sfM);
    cudaGetSymbolAddress((void**)&htB,   g_htB);
    cudaGetSymbolAddress((void**)&dp,    g_dp);
    cudaGetSymbolAddress((void**)&y1,    g_y1);
    cudaGetSymbolAddress((void**)&biasM, g_biasM);
    cudaGetSymbolAddress((void**)&gif,   g_if);
    cudaGetSymbolAddress((void**)&gie,   g_ie);
    cudaGetSymbolAddress((void**)&gfe,   g_fe);

    cudaFuncSetAttribute(gemm_mma_kernel<0>, cudaFuncAttributeMaxDynamicSharedMemorySize, GEMM_SMEM);
    cudaFuncSetAttribute(gemm_mma_kernel<1>, cudaFuncAttributeMaxDynamicSharedMemorySize, GEMM_SMEM);
    cudaFuncSetAttribute(gate_kernel, cudaFuncAttributeMaxDynamicSharedMemorySize, GW_SMEM);

    // 0: everything input-only (ln1+A-pack, all weight packs, bias) in one launch
    mega_pack_kernel<<<NB_TOTAL, 256>>>(x, ln1_g, ln1_b, W_up_l, W_up_r, W_skip,
                                        fused_W, W_down, fused_b,
                                        xnP, WupP, WsfP, WdP, biasM);

    // 1: merged up projection: [xt | rt] = xn @ [W_up_l; W_up_r]^T   (K3=2304)
    gemm_mma_kernel<0><<<dim3(NUP / 128, ROWS / 128), 128, GEMM_SMEM>>>(NUP, 3 * INP, xnP, WupP, nullptr, upM);

    // 2: conv + silu + fp16 A-pack
    conv_silu_pack_kernel<<<dim3(UPD / 512, ROWS), 128>>>(upM, conv_w, xcP);

    // 3: merged skip+fused GEMM (K=3072)  <- lands at absolute ncu slot 5
    gemm_mma_kernel<1><<<dim3((NSF + 127) / 128, ROWS / 128), 128, GEMM_SMEM>>>(NSF, 2 * UPD, xcP, WsfP, biasM, sfM);

    // 4: exact gates
    gate_kernel<<<ROWS / 16, 256, GW_SMEM>>>(xcP, fused_W, fused_b, gif);

    float* outC = out + (size_t)ROWS * INP;
    float* outN = outC + (size_t)BATCH * NH * HD * HD;
    float* outM = outN + (size_t)BATCH * NH * HD;
    // 5: parallel max-plus scan for gate exponentials
    mscan_kernel<<<BATCH * NH, SEQ>>>(gif, gie, gfe, outM);
    // 6: mLSTM state scan (e-split x4)
    scan_kernel<<<BATCH * NH * 4, 96>>>(sfM, gie, gfe, htB, dp, outC, outN);

    // 7: denom + o-gate + LN2 + fp16 A-pack
    post_pack_kernel<<<ROWS, 256>>>(sfM, htB, dp, ln2_g, ln2_b, hn2P);

    // 8: down projection (K=1536)
    gemm_mma_kernel<1><<<dim3(HID / 128, ROWS / 128), 128, GEMM_SMEM>>>(HID, 2 * HID, hn2P, WdP, nullptr, y1);

    // 9: final fuse
    final_kernel<<<ROWS, 192>>>(y1, sfM, upM, x, out);
}